// round 4
// baseline (speedup 1.0000x reference)
#include <cuda_runtime.h>
#include <math.h>
#include <stdint.h>

// ---------------- problem constants ----------------
#define BB    4
#define NN    8192
#define DD    1024
#define NHEAD 8
#define DHH   64
#define HIDD  512
#define WINN  128
#define NQQ   1024
#define NKVV  2048
#define NITERS 50
#define QK_SCALE 0.125f   // DH^-0.5

// ---------------- device scratch (no cudaMalloc allowed) ----------------
__device__ float g_rn   [BB*NN*DD];        // normalized x (x * sqrt(D)/||x||), gamma folded into weights
__device__ float g_qkv  [(size_t)BB*NN*1536]; // [q(512) | k(512) | v(512)] light
__device__ float g_attnl[BB*NN*HIDD];      // light attention output (pre-Wo)
__device__ float g_scores[2*BB*NN];        // routing scores: r=0 (q), r=1 (kv)
__device__ int   g_idxq [BB*NQQ];
__device__ int   g_idxkv[BB*NKVV];
__device__ float g_rnq  [BB*NQQ*DD];
__device__ float g_rnkv [BB*NKVV*DD];
__device__ float g_qh   [BB*NQQ*HIDD];
__device__ float g_kvh  [BB*NKVV*1024];    // per head: [k(64) | v(64)]
__device__ float g_attnh[BB*NQQ*HIDD];
__device__ float g_hrows[BB*NQQ*DD];
__device__ float g_Wl   [DD*1536];         // gamma_light-folded [wq_light | wkv_light]
__device__ float g_Wqh  [DD*HIDD];         // gamma_heavy-folded wq_heavy
__device__ float g_Wkvh [DD*1024];         // gamma_heavy-folded wkv_heavy^T (col = (h,d'))

// ---------------- weight prep ----------------
__global__ void prep_weights_kernel(const float* __restrict__ gl, const float* __restrict__ wql,
                                    const float* __restrict__ wkvl, const float* __restrict__ gh,
                                    const float* __restrict__ wqh, const float* __restrict__ wkvh)
{
    const int T1 = DD*1536, T2 = DD*HIDD, T3 = DD*1024;
    int i = blockIdx.x*blockDim.x + threadIdx.x;
    if (i < T1) {
        int d = i/1536, j = i%1536;
        float v = (j < 512) ? wql[d*512 + j] : wkvl[d*1024 + (j-512)];
        g_Wl[i] = gl[d]*v;
    } else if (i < T1+T2) {
        int t = i - T1; int d = t/512;
        g_Wqh[t] = gh[d]*wqh[t];
    } else if (i < T1+T2+T3) {
        int t = i - T1 - T2; int d = t/1024, j = t%1024;
        g_Wkvh[t] = gh[d]*wkvh[j*1024 + d];   // transpose [2HID,D] -> [D,2HID]
    }
}

// ---------------- rmsnorm (F.normalize * sqrt(D)) ----------------
__global__ void rmsnorm_kernel(const float* __restrict__ x)
{
    int row = blockIdx.x;                    // token row (b*N+n)
    const float4* xr = (const float4*)(x + (size_t)row*DD);
    float4 v = xr[threadIdx.x];
    float ss = v.x*v.x + v.y*v.y + v.z*v.z + v.w*v.w;
    __shared__ float red[8];
    for (int o=16;o;o>>=1) ss += __shfl_xor_sync(0xffffffffu, ss, o);
    if ((threadIdx.x&31)==0) red[threadIdx.x>>5] = ss;
    __syncthreads();
    if (threadIdx.x < 8) {
        float t = red[threadIdx.x];
        for (int o=4;o;o>>=1) t += __shfl_xor_sync(0xffu, t, o);
        if (threadIdx.x==0) red[0] = t;
    }
    __syncthreads();
    float norm = fmaxf(sqrtf(red[0]), 1e-12f);
    float sc = 32.0f / norm;                 // sqrt(1024)=32
    float4 o4 = make_float4(v.x*sc, v.y*sc, v.z*sc, v.w*sc);
    ((float4*)(g_rn + (size_t)row*DD))[threadIdx.x] = o4;
}

// ---------------- routing dot products ----------------
__global__ void routing_kernel(const float* __restrict__ x, const float* __restrict__ qt,
                               const float* __restrict__ kt)
{
    int gw = (blockIdx.x*blockDim.x + threadIdx.x) >> 5;
    int lane = threadIdx.x & 31;
    if (gw >= BB*NN) return;
    const float* xr = x + (size_t)gw*DD;
    float sq = 0.f, sk = 0.f;
    for (int j = lane; j < DD; j += 32) { float xv = xr[j]; sq += xv*qt[j]; sk += xv*kt[j]; }
    for (int o=16;o;o>>=1) { sq += __shfl_xor_sync(0xffffffffu, sq, o); sk += __shfl_xor_sync(0xffffffffu, sk, o); }
    if (lane==0) { g_scores[gw] = sq; g_scores[BB*NN + gw] = sk; }
}

// ---------------- coor_descent + exact top_k (bitonic sort with index tie-break) ----------------
__global__ __launch_bounds__(1024) void coor_topk_kernel()
{
    int r = blockIdx.x;     // 0=q routing, 1=kv routing
    int b = blockIdx.y;
    extern __shared__ unsigned long long keys[];   // 8192 u64
    __shared__ float red[32];
    int tid = threadIdx.x;
    const float* srow = g_scores + (size_t)r*BB*NN + (size_t)b*NN;
    float sv[8];
    {
        const float4* p = (const float4*)(srow + tid*8);
        float4 a0 = p[0], a1 = p[1];
        sv[0]=a0.x; sv[1]=a0.y; sv[2]=a0.z; sv[3]=a0.w;
        sv[4]=a1.x; sv[5]=a1.y; sv[6]=a1.z; sv[7]=a1.w;
    }
    float logk = logf(r==0 ? (float)NQQ*1.125f : (float)NKVV*1.125f);
    float a = 0.0f;
    for (int it=0; it<NITERS; ++it) {
        float v[8];
        if (it==0) {
            #pragma unroll
            for (int j=0;j<8;j++) v[j] = sv[j] + (-sv[j]);       // b0 = -s
        } else {
            #pragma unroll
            for (int j=0;j<8;j++) { float t = sv[j]+a; v[j] = sv[j] + (-fmaxf(t,0.0f)); }
        }
        float m = -INFINITY;
        #pragma unroll
        for (int j=0;j<8;j++) m = fmaxf(m, v[j]);
        for (int o=16;o;o>>=1) m = fmaxf(m, __shfl_xor_sync(0xffffffffu, m, o));
        if ((tid&31)==0) red[tid>>5] = m;
        __syncthreads();
        if (tid < 32) {
            float t = red[tid];
            for (int o=16;o;o>>=1) t = fmaxf(t, __shfl_xor_sync(0xffffffffu, t, o));
            if (tid==0) red[0] = t;
        }
        __syncthreads();
        m = red[0];
        __syncthreads();
        float s_ = 0.f;
        #pragma unroll
        for (int j=0;j<8;j++) s_ += expf(v[j] - m);
        for (int o=16;o;o>>=1) s_ += __shfl_xor_sync(0xffffffffu, s_, o);
        if ((tid&31)==0) red[tid>>5] = s_;
        __syncthreads();
        if (tid < 32) {
            float t = red[tid];
            for (int o=16;o;o>>=1) t += __shfl_xor_sync(0xffffffffu, t, o);
            if (tid==0) red[0] = t;
        }
        __syncthreads();
        float lse = logf(red[0]) + m;
        __syncthreads();
        a = logk - lse;
    }
    // final scores: exp(min(s+a,0)) computed exactly as jax: exp(s + a + b), b=-relu(s+a)
    #pragma unroll
    for (int j=0;j<8;j++) {
        int i = tid*8 + j;
        float t = sv[j] + a;
        float sc = expf(t + (-fmaxf(t, 0.0f)));
        unsigned int bits = __float_as_uint(sc);    // scores >=0 -> bit pattern is order-preserving
        keys[i] = ((unsigned long long)bits << 32) | (unsigned long long)(0xFFFFFFFFu - (unsigned)i);
    }
    __syncthreads();
    // bitonic sort descending (ties -> lower index first, matching jax.lax.top_k)
    for (unsigned k = 2; k <= 8192; k <<= 1) {
        for (unsigned j = k >> 1; j > 0; j >>= 1) {
            for (unsigned i = tid; i < 8192; i += 1024) {
                unsigned ixj = i ^ j;
                if (ixj > i) {
                    bool desc = ((i & k) == 0);
                    unsigned long long A = keys[i], Bk = keys[ixj];
                    bool sw = desc ? (A < Bk) : (A > Bk);
                    if (sw) { keys[i] = Bk; keys[ixj] = A; }
                }
            }
            __syncthreads();
        }
    }
    int NT = (r==0) ? NQQ : NKVV;
    int* outp = (r==0) ? (g_idxq + b*NQQ) : (g_idxkv + b*NKVV);
    for (int i = tid; i < NT; i += 1024)
        outp[i] = (int)(0xFFFFFFFFu - (unsigned)(keys[i] & 0xFFFFFFFFull));
}

// ---------------- gathers ----------------
__global__ void gather_kernel(int which)   // 0: q, 1: kv
{
    int row = blockIdx.x;
    int nt = which ? NKVV : NQQ;
    int b = row / nt;
    int src = which ? g_idxkv[row] : g_idxq[row];
    const float4* s = (const float4*)(g_rn + ((size_t)b*NN + src)*DD);
    float4* d = (float4*)((which ? g_rnkv : g_rnq) + (size_t)row*DD);
    d[threadIdx.x] = s[threadIdx.x];
}

// ---------------- SGEMM: C[M,N] = A[M,K] @ B[K,N] (all row-major, dims %128/%16) ----------------
__global__ __launch_bounds__(256) void sgemm_kernel(const float* __restrict__ A, const float* __restrict__ Bm,
                                                    float* __restrict__ C, int M, int Nc, int K)
{
    __shared__ float As[16*132];
    __shared__ float Bs[16*132];
    int tid = threadIdx.x;
    int tx = tid & 15, ty = tid >> 4;
    int bm = blockIdx.y * 128, bn = blockIdx.x * 128;
    float acc[8][8];
    #pragma unroll
    for (int i=0;i<8;i++)
        #pragma unroll
        for (int j=0;j<8;j++) acc[i][j] = 0.f;

    for (int kt = 0; kt < K; kt += 16) {
        #pragma unroll
        for (int q=0;q<2;q++) {
            int li = tid + q*256;
            int row = li >> 2;
            int k4 = (li & 3) * 4;
            float4 v = *(const float4*)(A + (size_t)(bm+row)*K + kt + k4);
            As[(k4+0)*132+row]=v.x; As[(k4+1)*132+row]=v.y; As[(k4+2)*132+row]=v.z; As[(k4+3)*132+row]=v.w;
        }
        #pragma unroll
        for (int q=0;q<2;q++) {
            int li = tid + q*256;
            int kk = li >> 5;
            int n4 = (li & 31) * 4;
            float4 v = *(const float4*)(Bm + (size_t)(kt+kk)*Nc + bn + n4);
            *(float4*)(Bs + kk*132 + n4) = v;
        }
        __syncthreads();
        #pragma unroll
        for (int kk=0;kk<16;kk++) {
            float af[8], bf[8];
            #pragma unroll
            for (int i=0;i<8;i++) af[i] = As[kk*132 + ty*8 + i];
            #pragma unroll
            for (int j=0;j<8;j++) bf[j] = Bs[kk*132 + tx*8 + j];
            #pragma unroll
            for (int i=0;i<8;i++)
                #pragma unroll
                for (int j=0;j<8;j++) acc[i][j] += af[i]*bf[j];
        }
        __syncthreads();
    }
    #pragma unroll
    for (int i=0;i<8;i++) {
        float* cp = C + (size_t)(bm+ty*8+i)*Nc + bn + tx*8;
        *(float4*)cp     = make_float4(acc[i][0],acc[i][1],acc[i][2],acc[i][3]);
        *(float4*)(cp+4) = make_float4(acc[i][4],acc[i][5],acc[i][6],acc[i][7]);
    }
}

// ---------------- light windowed attention (128 tokens / window) ----------------
__global__ __launch_bounds__(256) void winattn_kernel()
{
    extern __shared__ float sm[];
    float* Qs = sm;                // 128*65
    float* Ks = Qs + 128*65;
    float* Vs = Ks + 128*65;
    float* Ss = Vs + 128*65;       // 128*129
    int bx = blockIdx.x;
    int h = bx & 7, win = (bx>>3) & 63, b = bx >> 9;
    int base = b*NN + win*WINN;
    int tid = threadIdx.x;
    #pragma unroll
    for (int t=0;t<8;t++) {
        int li = tid + t*256;
        int row = li >> 4, c4 = (li & 15) * 4;
        const float* src = g_qkv + (size_t)(base+row)*1536;
        float4 q = *(const float4*)(src + h*64 + c4);
        float4 k = *(const float4*)(src + 512 + h*64 + c4);
        float4 v = *(const float4*)(src + 1024 + h*64 + c4);
        float* qp = Qs + row*65 + c4;
        qp[0]=q.x*QK_SCALE; qp[1]=q.y*QK_SCALE; qp[2]=q.z*QK_SCALE; qp[3]=q.w*QK_SCALE;
        float* kp = Ks + row*65 + c4; kp[0]=k.x; kp[1]=k.y; kp[2]=k.z; kp[3]=k.w;
        float* vp = Vs + row*65 + c4; vp[0]=v.x; vp[1]=v.y; vp[2]=v.z; vp[3]=v.w;
    }
    __syncthreads();
    int tx = tid & 15, ty = tid >> 4;
    float acc[8][8];
    #pragma unroll
    for (int i=0;i<8;i++)
        #pragma unroll
        for (int j=0;j<8;j++) acc[i][j]=0.f;
    for (int d=0; d<64; d++) {
        float af[8], bf[8];
        #pragma unroll
        for (int i=0;i<8;i++) af[i] = Qs[(ty*8+i)*65 + d];
        #pragma unroll
        for (int j=0;j<8;j++) bf[j] = Ks[(tx*8+j)*65 + d];
        #pragma unroll
        for (int i=0;i<8;i++)
            #pragma unroll
            for (int j=0;j<8;j++) acc[i][j] += af[i]*bf[j];
    }
    #pragma unroll
    for (int i=0;i<8;i++)
        #pragma unroll
        for (int j=0;j<8;j++) Ss[(ty*8+i)*129 + tx*8 + j] = acc[i][j];
    __syncthreads();
    if (tid < 128) {
        float* row = Ss + tid*129;
        float m = -INFINITY;
        for (int k=0;k<128;k++) m = fmaxf(m, row[k]);
        float s = 0.f;
        for (int k=0;k<128;k++) { float e = expf(row[k]-m); row[k]=e; s += e; }
        float inv = 1.0f/s;
        for (int k=0;k<128;k++) row[k] *= inv;
    }
    __syncthreads();
    int orow = tid >> 1, cb = (tid & 1) * 32;
    float o[32];
    #pragma unroll
    for (int c=0;c<32;c++) o[c]=0.f;
    for (int k=0;k<128;k++) {
        float p = Ss[orow*129 + k];
        const float* vp = Vs + k*65 + cb;
        #pragma unroll
        for (int c=0;c<32;c++) o[c] += p*vp[c];
    }
    float* outp = g_attnl + (size_t)(base+orow)*512 + h*64 + cb;
    #pragma unroll
    for (int c=0;c<32;c++) outp[c] = o[c];
}

// ---------------- heavy attention (flash-style over NKV=2048) ----------------
__global__ __launch_bounds__(256) void heavyattn_kernel()
{
    extern __shared__ float sm[];
    float* Qs = sm;
    float* Ks = Qs + 128*65;
    float* Vs = Ks + 128*65;
    float* Ss = Vs + 128*65;           // 128*129
    float* mrow = Ss + 128*129;
    float* lrow = mrow + 128;
    float* crow = lrow + 128;
    int bx = blockIdx.x;
    int qt = bx & 7, h = (bx>>3) & 7, b = bx >> 6;
    int tid = threadIdx.x;
    #pragma unroll
    for (int t=0;t<8;t++) {
        int li = tid + t*256;
        int row = li >> 4, c4 = (li & 15) * 4;
        float4 q = *(const float4*)(g_qh + (size_t)(b*NQQ + qt*128 + row)*512 + h*64 + c4);
        float* qp = Qs + row*65 + c4;
        qp[0]=q.x*QK_SCALE; qp[1]=q.y*QK_SCALE; qp[2]=q.z*QK_SCALE; qp[3]=q.w*QK_SCALE;
    }
    if (tid < 128) { mrow[tid] = -INFINITY; lrow[tid] = 0.f; }
    int orow = tid >> 1, cb = (tid & 1) * 32;
    float o[32];
    #pragma unroll
    for (int c=0;c<32;c++) o[c]=0.f;
    int tx = tid & 15, ty = tid >> 4;
    __syncthreads();
    for (int it=0; it<NKVV/128; ++it) {
        __syncthreads();   // previous O update finished before overwriting tiles
        #pragma unroll
        for (int t=0;t<8;t++) {
            int li = tid + t*256;
            int row = li >> 4, c4 = (li & 15) * 4;
            const float* src = g_kvh + (size_t)(b*NKVV + it*128 + row)*1024 + h*128;
            float4 k = *(const float4*)(src + c4);
            float4 v = *(const float4*)(src + 64 + c4);
            float* kp = Ks + row*65 + c4; kp[0]=k.x; kp[1]=k.y; kp[2]=k.z; kp[3]=k.w;
            float* vp = Vs + row*65 + c4; vp[0]=v.x; vp[1]=v.y; vp[2]=v.z; vp[3]=v.w;
        }
        __syncthreads();
        float acc[8][8];
        #pragma unroll
        for (int i=0;i<8;i++)
            #pragma unroll
            for (int j=0;j<8;j++) acc[i][j]=0.f;
        for (int d=0; d<64; d++) {
            float af[8], bf[8];
            #pragma unroll
            for (int i=0;i<8;i++) af[i] = Qs[(ty*8+i)*65 + d];
            #pragma unroll
            for (int j=0;j<8;j++) bf[j] = Ks[(tx*8+j)*65 + d];
            #pragma unroll
            for (int i=0;i<8;i++)
                #pragma unroll
                for (int j=0;j<8;j++) acc[i][j] += af[i]*bf[j];
        }
        #pragma unroll
        for (int i=0;i<8;i++)
            #pragma unroll
            for (int j=0;j<8;j++) Ss[(ty*8+i)*129 + tx*8 + j] = acc[i][j];
        __syncthreads();
        if (tid < 128) {
            float* row = Ss + tid*129;
            float mold = mrow[tid];
            float mx = mold;
            for (int k=0;k<128;k++) mx = fmaxf(mx, row[k]);
            float corr = expf(mold - mx);
            float s = 0.f;
            for (int k=0;k<128;k++) { float e = expf(row[k]-mx); row[k]=e; s += e; }
            lrow[tid] = lrow[tid]*corr + s;
            mrow[tid] = mx;
            crow[tid] = corr;
        }
        __syncthreads();
        float corr = crow[orow];
        #pragma unroll
        for (int c=0;c<32;c++) o[c] *= corr;
        for (int k=0;k<128;k++) {
            float p = Ss[orow*129 + k];
            const float* vp = Vs + k*65 + cb;
            #pragma unroll
            for (int c=0;c<32;c++) o[c] += p*vp[c];
        }
    }
    __syncthreads();
    float inv = 1.0f / lrow[orow];
    float* outp = g_attnh + (size_t)(b*NQQ + qt*128 + orow)*512 + h*64 + cb;
    #pragma unroll
    for (int c=0;c<32;c++) outp[c] = o[c]*inv;
}

// ---------------- scatter-add heavy rows into output ----------------
__global__ void scatter_kernel(float* __restrict__ out)
{
    int rowi = blockIdx.x;               // 0..B*NQ-1
    int b = rowi >> 10;
    int dst = g_idxq[rowi];
    float4* o = (float4*)(out + ((size_t)b*NN + dst)*DD);
    const float4* s = (const float4*)(g_hrows + (size_t)rowi*DD);
    float4 a = o[threadIdx.x];
    float4 v = s[threadIdx.x];
    a.x += v.x; a.y += v.y; a.z += v.z; a.w += v.w;
    o[threadIdx.x] = a;
}

// ---------------- launch ----------------
extern "C" void kernel_launch(void* const* d_in, const int* in_sizes, int n_in,
                              void* d_out, int out_size)
{
    const float* x       = (const float*)d_in[0];
    const float* gamma_l = (const float*)d_in[1];
    const float* wq_l    = (const float*)d_in[2];
    const float* wkv_l   = (const float*)d_in[3];
    const float* wo_l    = (const float*)d_in[4];
    const float* qtok    = (const float*)d_in[5];
    const float* ktok    = (const float*)d_in[6];
    const float* gamma_h = (const float*)d_in[7];
    const float* wq_h    = (const float*)d_in[8];
    const float* wkv_h   = (const float*)d_in[9];
    const float* wo_h    = (const float*)d_in[10];
    float* out = (float*)d_out;

    float *p_rn, *p_qkv, *p_attnl, *p_rnq, *p_rnkv, *p_qh, *p_kvh, *p_attnh, *p_hrows;
    float *p_Wl, *p_Wqh, *p_Wkvh;
    cudaGetSymbolAddress((void**)&p_rn,    g_rn);
    cudaGetSymbolAddress((void**)&p_qkv,   g_qkv);
    cudaGetSymbolAddress((void**)&p_attnl, g_attnl);
    cudaGetSymbolAddress((void**)&p_rnq,   g_rnq);
    cudaGetSymbolAddress((void**)&p_rnkv,  g_rnkv);
    cudaGetSymbolAddress((void**)&p_qh,    g_qh);
    cudaGetSymbolAddress((void**)&p_kvh,   g_kvh);
    cudaGetSymbolAddress((void**)&p_attnh, g_attnh);
    cudaGetSymbolAddress((void**)&p_hrows, g_hrows);
    cudaGetSymbolAddress((void**)&p_Wl,    g_Wl);
    cudaGetSymbolAddress((void**)&p_Wqh,   g_Wqh);
    cudaGetSymbolAddress((void**)&p_Wkvh,  g_Wkvh);

    const int SMEM_SORT  = 8192 * 8;                              // 64 KB
    const int SMEM_WIN   = (3*128*65 + 128*129) * 4;              // 165888
    const int SMEM_HEAVY = (3*128*65 + 128*129 + 3*128) * 4;      // 167424
    cudaFuncSetAttribute(coor_topk_kernel, cudaFuncAttributeMaxDynamicSharedMemorySize, SMEM_SORT);
    cudaFuncSetAttribute(winattn_kernel,   cudaFuncAttributeMaxDynamicSharedMemorySize, SMEM_WIN);
    cudaFuncSetAttribute(heavyattn_kernel, cudaFuncAttributeMaxDynamicSharedMemorySize, SMEM_HEAVY);

    // 1) weight prep (fold gammas, transpose wkv_heavy)
    {
        int tot = DD*1536 + DD*HIDD + DD*1024;
        prep_weights_kernel<<<(tot+255)/256, 256>>>(gamma_l, wq_l, wkv_l, gamma_h, wq_h, wkv_h);
    }
    // 2) rmsnorm of all tokens
    rmsnorm_kernel<<<BB*NN, 256>>>(x);
    // 3) routing scores (raw x)
    routing_kernel<<<BB*NN/8, 256>>>(x, qtok, ktok);
    // 4) coor_descent + exact top-k selection
    coor_topk_kernel<<<dim3(2, BB), 1024, SMEM_SORT>>>();
    // 5) gather routed normalized rows
    gather_kernel<<<BB*NQQ,  256>>>(0);
    gather_kernel<<<BB*NKVV, 256>>>(1);
    // 6) light qkv projection (fused wq|wkv)
    sgemm_kernel<<<dim3(1536/128, (BB*NN)/128), 256>>>(p_rn, p_Wl, p_qkv, BB*NN, 1536, DD);
    // 7) light windowed attention
    winattn_kernel<<<BB*(NN/WINN)*NHEAD, 256, SMEM_WIN>>>();
    // 8) light output projection -> d_out (writes every element)
    sgemm_kernel<<<dim3(DD/128, (BB*NN)/128), 256>>>(p_attnl, wo_l, out, BB*NN, DD, HIDD);
    // 9) heavy projections
    sgemm_kernel<<<dim3(HIDD/128, (BB*NQQ)/128), 256>>>(p_rnq,  p_Wqh,  p_qh,  BB*NQQ,  HIDD, DD);
    sgemm_kernel<<<dim3(1024/128, (BB*NKVV)/128), 256>>>(p_rnkv, p_Wkvh, p_kvh, BB*NKVV, 1024, DD);
    // 10) heavy attention (flash over 2048 kv)
    heavyattn_kernel<<<BB*NHEAD*(NQQ/128), 256, SMEM_HEAVY>>>();
    // 11) heavy output projection
    sgemm_kernel<<<dim3(DD/128, (BB*NQQ)/128), 256>>>(p_attnh, wo_h, p_hrows, BB*NQQ, DD, HIDD);
    // 12) scatter-add into output
    scatter_kernel<<<BB*NQQ, 256>>>(out);
}

// round 5
// speedup vs baseline: 1.0012x; 1.0012x over previous
#include <cuda_runtime.h>
#include <math.h>
#include <stdint.h>

// ---------------- problem constants ----------------
#define BB    4
#define NN    8192
#define DD    1024
#define NHEAD 8
#define DHH   64
#define HIDD  512
#define WINN  128
#define NQQ   1024
#define NKVV  2048
#define NITERS 50
#define QK_SCALE 0.125f   // DH^-0.5

// ---------------- device scratch (no cudaMalloc allowed) ----------------
__device__ float g_rn   [BB*NN*DD];        // normalized x (x * sqrt(D)/||x||), gamma folded into weights
__device__ float g_qkv  [(size_t)BB*NN*1536]; // [q(512) | k(512) | v(512)] light
__device__ float g_attnl[BB*NN*HIDD];      // light attention output (pre-Wo)
__device__ float g_scores[2*BB*NN];        // routing scores: r=0 (q), r=1 (kv)
__device__ int   g_idxq [BB*NQQ];
__device__ int   g_idxkv[BB*NKVV];
__device__ float g_rnq  [BB*NQQ*DD];
__device__ float g_rnkv [BB*NKVV*DD];
__device__ float g_qh   [BB*NQQ*HIDD];
__device__ float g_kvh  [BB*NKVV*1024];    // per head: [k(64) | v(64)]
__device__ float g_attnh[BB*NQQ*HIDD];
__device__ float g_hrows[BB*NQQ*DD];
__device__ float g_Wl   [DD*1536];         // gamma_light-folded [wq_light | wkv_light]
__device__ float g_Wqh  [DD*HIDD];         // gamma_heavy-folded wq_heavy
__device__ float g_Wkvh [DD*1024];         // gamma_heavy-folded wkv_heavy^T (col = (h,d'))

// ---------------- weight prep ----------------
__global__ void prep_weights_kernel(const float* __restrict__ gl, const float* __restrict__ wql,
                                    const float* __restrict__ wkvl, const float* __restrict__ gh,
                                    const float* __restrict__ wqh, const float* __restrict__ wkvh)
{
    const int T1 = DD*1536, T2 = DD*HIDD, T3 = DD*1024;
    int i = blockIdx.x*blockDim.x + threadIdx.x;
    if (i < T1) {
        int d = i/1536, j = i%1536;
        float v = (j < 512) ? wql[d*512 + j] : wkvl[d*1024 + (j-512)];
        g_Wl[i] = gl[d]*v;
    } else if (i < T1+T2) {
        int t = i - T1; int d = t/512;
        g_Wqh[t] = gh[d]*wqh[t];
    } else if (i < T1+T2+T3) {
        int t = i - T1 - T2; int d = t/1024, j = t%1024;
        g_Wkvh[t] = gh[d]*wkvh[j*1024 + d];   // transpose [2HID,D] -> [D,2HID]
    }
}

// ---------------- rmsnorm (F.normalize * sqrt(D)) ----------------
__global__ void rmsnorm_kernel(const float* __restrict__ x)
{
    int row = blockIdx.x;                    // token row (b*N+n)
    const float4* xr = (const float4*)(x + (size_t)row*DD);
    float4 v = xr[threadIdx.x];
    float ss = v.x*v.x + v.y*v.y + v.z*v.z + v.w*v.w;
    __shared__ float red[8];
    for (int o=16;o;o>>=1) ss += __shfl_xor_sync(0xffffffffu, ss, o);
    if ((threadIdx.x&31)==0) red[threadIdx.x>>5] = ss;
    __syncthreads();
    if (threadIdx.x < 8) {
        float t = red[threadIdx.x];
        for (int o=4;o;o>>=1) t += __shfl_xor_sync(0xffu, t, o);
        if (threadIdx.x==0) red[0] = t;
    }
    __syncthreads();
    float norm = fmaxf(sqrtf(red[0]), 1e-12f);
    float sc = 32.0f / norm;                 // sqrt(1024)=32
    float4 o4 = make_float4(v.x*sc, v.y*sc, v.z*sc, v.w*sc);
    ((float4*)(g_rn + (size_t)row*DD))[threadIdx.x] = o4;
}

// ---------------- routing dot products ----------------
__global__ void routing_kernel(const float* __restrict__ x, const float* __restrict__ qt,
                               const float* __restrict__ kt)
{
    int gw = (blockIdx.x*blockDim.x + threadIdx.x) >> 5;
    int lane = threadIdx.x & 31;
    if (gw >= BB*NN) return;
    const float* xr = x + (size_t)gw*DD;
    float sq = 0.f, sk = 0.f;
    for (int j = lane; j < DD; j += 32) { float xv = xr[j]; sq += xv*qt[j]; sk += xv*kt[j]; }
    for (int o=16;o;o>>=1) { sq += __shfl_xor_sync(0xffffffffu, sq, o); sk += __shfl_xor_sync(0xffffffffu, sk, o); }
    if (lane==0) { g_scores[gw] = sq; g_scores[BB*NN + gw] = sk; }
}

// ---------------- coor_descent + exact top_k (bitonic sort with index tie-break) ----------------
__global__ __launch_bounds__(1024) void coor_topk_kernel()
{
    int r = blockIdx.x;     // 0=q routing, 1=kv routing
    int b = blockIdx.y;
    extern __shared__ unsigned long long keys[];   // 8192 u64
    __shared__ float red[32];
    int tid = threadIdx.x;
    const float* srow = g_scores + (size_t)r*BB*NN + (size_t)b*NN;
    float sv[8];
    {
        const float4* p = (const float4*)(srow + tid*8);
        float4 a0 = p[0], a1 = p[1];
        sv[0]=a0.x; sv[1]=a0.y; sv[2]=a0.z; sv[3]=a0.w;
        sv[4]=a1.x; sv[5]=a1.y; sv[6]=a1.z; sv[7]=a1.w;
    }
    float logk = logf(r==0 ? (float)NQQ*1.125f : (float)NKVV*1.125f);
    float a = 0.0f;
    for (int it=0; it<NITERS; ++it) {
        float v[8];
        if (it==0) {
            #pragma unroll
            for (int j=0;j<8;j++) v[j] = sv[j] + (-sv[j]);       // b0 = -s
        } else {
            #pragma unroll
            for (int j=0;j<8;j++) { float t = sv[j]+a; v[j] = sv[j] + (-fmaxf(t,0.0f)); }
        }
        float m = -INFINITY;
        #pragma unroll
        for (int j=0;j<8;j++) m = fmaxf(m, v[j]);
        for (int o=16;o;o>>=1) m = fmaxf(m, __shfl_xor_sync(0xffffffffu, m, o));
        if ((tid&31)==0) red[tid>>5] = m;
        __syncthreads();
        if (tid < 32) {
            float t = red[tid];
            for (int o=16;o;o>>=1) t = fmaxf(t, __shfl_xor_sync(0xffffffffu, t, o));
            if (tid==0) red[0] = t;
        }
        __syncthreads();
        m = red[0];
        __syncthreads();
        float s_ = 0.f;
        #pragma unroll
        for (int j=0;j<8;j++) s_ += expf(v[j] - m);
        for (int o=16;o;o>>=1) s_ += __shfl_xor_sync(0xffffffffu, s_, o);
        if ((tid&31)==0) red[tid>>5] = s_;
        __syncthreads();
        if (tid < 32) {
            float t = red[tid];
            for (int o=16;o;o>>=1) t += __shfl_xor_sync(0xffffffffu, t, o);
            if (tid==0) red[0] = t;
        }
        __syncthreads();
        float lse = logf(red[0]) + m;
        __syncthreads();
        a = logk - lse;
    }
    // final scores: exp(min(s+a,0)) computed exactly as jax: exp(s + a + b), b=-relu(s+a)
    #pragma unroll
    for (int j=0;j<8;j++) {
        int i = tid*8 + j;
        float t = sv[j] + a;
        float sc = expf(t + (-fmaxf(t, 0.0f)));
        unsigned int bits = __float_as_uint(sc);    // scores >=0 -> bit pattern is order-preserving
        keys[i] = ((unsigned long long)bits << 32) | (unsigned long long)(0xFFFFFFFFu - (unsigned)i);
    }
    __syncthreads();
    // bitonic sort descending (ties -> lower index first, matching jax.lax.top_k)
    for (unsigned k = 2; k <= 8192; k <<= 1) {
        for (unsigned j = k >> 1; j > 0; j >>= 1) {
            for (unsigned i = tid; i < 8192; i += 1024) {
                unsigned ixj = i ^ j;
                if (ixj > i) {
                    bool desc = ((i & k) == 0);
                    unsigned long long A = keys[i], Bk = keys[ixj];
                    bool sw = desc ? (A < Bk) : (A > Bk);
                    if (sw) { keys[i] = Bk; keys[ixj] = A; }
                }
            }
            __syncthreads();
        }
    }
    int NT = (r==0) ? NQQ : NKVV;
    int* outp = (r==0) ? (g_idxq + b*NQQ) : (g_idxkv + b*NKVV);
    for (int i = tid; i < NT; i += 1024)
        outp[i] = (int)(0xFFFFFFFFu - (unsigned)(keys[i] & 0xFFFFFFFFull));
}

// ---------------- gathers ----------------
__global__ void gather_kernel(int which)   // 0: q, 1: kv
{
    int row = blockIdx.x;
    int nt = which ? NKVV : NQQ;
    int b = row / nt;
    int src = which ? g_idxkv[row] : g_idxq[row];
    const float4* s = (const float4*)(g_rn + ((size_t)b*NN + src)*DD);
    float4* d = (float4*)((which ? g_rnkv : g_rnq) + (size_t)row*DD);
    d[threadIdx.x] = s[threadIdx.x];
}

// ---------------- SGEMM: C[M,N] = A[M,K] @ B[K,N] (all row-major, dims %128/%16) ----------------
__global__ __launch_bounds__(256) void sgemm_kernel(const float* __restrict__ A, const float* __restrict__ Bm,
                                                    float* __restrict__ C, int M, int Nc, int K)
{
    __shared__ float As[16*132];
    __shared__ float Bs[16*132];
    int tid = threadIdx.x;
    int tx = tid & 15, ty = tid >> 4;
    int bm = blockIdx.y * 128, bn = blockIdx.x * 128;
    float acc[8][8];
    #pragma unroll
    for (int i=0;i<8;i++)
        #pragma unroll
        for (int j=0;j<8;j++) acc[i][j] = 0.f;

    for (int kt = 0; kt < K; kt += 16) {
        #pragma unroll
        for (int q=0;q<2;q++) {
            int li = tid + q*256;
            int row = li >> 2;
            int k4 = (li & 3) * 4;
            float4 v = *(const float4*)(A + (size_t)(bm+row)*K + kt + k4);
            As[(k4+0)*132+row]=v.x; As[(k4+1)*132+row]=v.y; As[(k4+2)*132+row]=v.z; As[(k4+3)*132+row]=v.w;
        }
        #pragma unroll
        for (int q=0;q<2;q++) {
            int li = tid + q*256;
            int kk = li >> 5;
            int n4 = (li & 31) * 4;
            float4 v = *(const float4*)(Bm + (size_t)(kt+kk)*Nc + bn + n4);
            *(float4*)(Bs + kk*132 + n4) = v;
        }
        __syncthreads();
        #pragma unroll
        for (int kk=0;kk<16;kk++) {
            float af[8], bf[8];
            #pragma unroll
            for (int i=0;i<8;i++) af[i] = As[kk*132 + ty*8 + i];
            #pragma unroll
            for (int j=0;j<8;j++) bf[j] = Bs[kk*132 + tx*8 + j];
            #pragma unroll
            for (int i=0;i<8;i++)
                #pragma unroll
                for (int j=0;j<8;j++) acc[i][j] += af[i]*bf[j];
        }
        __syncthreads();
    }
    #pragma unroll
    for (int i=0;i<8;i++) {
        float* cp = C + (size_t)(bm+ty*8+i)*Nc + bn + tx*8;
        *(float4*)cp     = make_float4(acc[i][0],acc[i][1],acc[i][2],acc[i][3]);
        *(float4*)(cp+4) = make_float4(acc[i][4],acc[i][5],acc[i][6],acc[i][7]);
    }
}

// ---------------- light windowed attention (128 tokens / window) ----------------
__global__ __launch_bounds__(256) void winattn_kernel()
{
    extern __shared__ float sm[];
    float* Qs = sm;                // 128*65
    float* Ks = Qs + 128*65;
    float* Vs = Ks + 128*65;
    float* Ss = Vs + 128*65;       // 128*129
    int bx = blockIdx.x;
    int h = bx & 7, win = (bx>>3) & 63, b = bx >> 9;
    int base = b*NN + win*WINN;
    int tid = threadIdx.x;
    #pragma unroll
    for (int t=0;t<8;t++) {
        int li = tid + t*256;
        int row = li >> 4, c4 = (li & 15) * 4;
        const float* src = g_qkv + (size_t)(base+row)*1536;
        float4 q = *(const float4*)(src + h*64 + c4);
        float4 k = *(const float4*)(src + 512 + h*64 + c4);
        float4 v = *(const float4*)(src + 1024 + h*64 + c4);
        float* qp = Qs + row*65 + c4;
        qp[0]=q.x*QK_SCALE; qp[1]=q.y*QK_SCALE; qp[2]=q.z*QK_SCALE; qp[3]=q.w*QK_SCALE;
        float* kp = Ks + row*65 + c4; kp[0]=k.x; kp[1]=k.y; kp[2]=k.z; kp[3]=k.w;
        float* vp = Vs + row*65 + c4; vp[0]=v.x; vp[1]=v.y; vp[2]=v.z; vp[3]=v.w;
    }
    __syncthreads();
    int tx = tid & 15, ty = tid >> 4;
    float acc[8][8];
    #pragma unroll
    for (int i=0;i<8;i++)
        #pragma unroll
        for (int j=0;j<8;j++) acc[i][j]=0.f;
    for (int d=0; d<64; d++) {
        float af[8], bf[8];
        #pragma unroll
        for (int i=0;i<8;i++) af[i] = Qs[(ty*8+i)*65 + d];
        #pragma unroll
        for (int j=0;j<8;j++) bf[j] = Ks[(tx*8+j)*65 + d];
        #pragma unroll
        for (int i=0;i<8;i++)
            #pragma unroll
            for (int j=0;j<8;j++) acc[i][j] += af[i]*bf[j];
    }
    #pragma unroll
    for (int i=0;i<8;i++)
        #pragma unroll
        for (int j=0;j<8;j++) Ss[(ty*8+i)*129 + tx*8 + j] = acc[i][j];
    __syncthreads();
    if (tid < 128) {
        float* row = Ss + tid*129;
        float m = -INFINITY;
        for (int k=0;k<128;k++) m = fmaxf(m, row[k]);
        float s = 0.f;
        for (int k=0;k<128;k++) { float e = expf(row[k]-m); row[k]=e; s += e; }
        float inv = 1.0f/s;
        for (int k=0;k<128;k++) row[k] *= inv;
    }
    __syncthreads();
    int orow = tid >> 1, cb = (tid & 1) * 32;
    float o[32];
    #pragma unroll
    for (int c=0;c<32;c++) o[c]=0.f;
    for (int k=0;k<128;k++) {
        float p = Ss[orow*129 + k];
        const float* vp = Vs + k*65 + cb;
        #pragma unroll
        for (int c=0;c<32;c++) o[c] += p*vp[c];
    }
    float* outp = g_attnl + (size_t)(base+orow)*512 + h*64 + cb;
    #pragma unroll
    for (int c=0;c<32;c++) outp[c] = o[c];
}

// ---------------- heavy attention (flash-style over NKV=2048) ----------------
__global__ __launch_bounds__(256) void heavyattn_kernel()
{
    extern __shared__ float sm[];
    float* Qs = sm;
    float* Ks = Qs + 128*65;
    float* Vs = Ks + 128*65;
    float* Ss = Vs + 128*65;           // 128*129
    float* mrow = Ss + 128*129;
    float* lrow = mrow + 128;
    float* crow = lrow + 128;
    int bx = blockIdx.x;
    int qt = bx & 7, h = (bx>>3) & 7, b = bx >> 6;
    int tid = threadIdx.x;
    #pragma unroll
    for (int t=0;t<8;t++) {
        int li = tid + t*256;
        int row = li >> 4, c4 = (li & 15) * 4;
        float4 q = *(const float4*)(g_qh + (size_t)(b*NQQ + qt*128 + row)*512 + h*64 + c4);
        float* qp = Qs + row*65 + c4;
        qp[0]=q.x*QK_SCALE; qp[1]=q.y*QK_SCALE; qp[2]=q.z*QK_SCALE; qp[3]=q.w*QK_SCALE;
    }
    if (tid < 128) { mrow[tid] = -INFINITY; lrow[tid] = 0.f; }
    int orow = tid >> 1, cb = (tid & 1) * 32;
    float o[32];
    #pragma unroll
    for (int c=0;c<32;c++) o[c]=0.f;
    int tx = tid & 15, ty = tid >> 4;
    __syncthreads();
    for (int it=0; it<NKVV/128; ++it) {
        __syncthreads();   // previous O update finished before overwriting tiles
        #pragma unroll
        for (int t=0;t<8;t++) {
            int li = tid + t*256;
            int row = li >> 4, c4 = (li & 15) * 4;
            const float* src = g_kvh + (size_t)(b*NKVV + it*128 + row)*1024 + h*128;
            float4 k = *(const float4*)(src + c4);
            float4 v = *(const float4*)(src + 64 + c4);
            float* kp = Ks + row*65 + c4; kp[0]=k.x; kp[1]=k.y; kp[2]=k.z; kp[3]=k.w;
            float* vp = Vs + row*65 + c4; vp[0]=v.x; vp[1]=v.y; vp[2]=v.z; vp[3]=v.w;
        }
        __syncthreads();
        float acc[8][8];
        #pragma unroll
        for (int i=0;i<8;i++)
            #pragma unroll
            for (int j=0;j<8;j++) acc[i][j]=0.f;
        for (int d=0; d<64; d++) {
            float af[8], bf[8];
            #pragma unroll
            for (int i=0;i<8;i++) af[i] = Qs[(ty*8+i)*65 + d];
            #pragma unroll
            for (int j=0;j<8;j++) bf[j] = Ks[(tx*8+j)*65 + d];
            #pragma unroll
            for (int i=0;i<8;i++)
                #pragma unroll
                for (int j=0;j<8;j++) acc[i][j] += af[i]*bf[j];
        }
        #pragma unroll
        for (int i=0;i<8;i++)
            #pragma unroll
            for (int j=0;j<8;j++) Ss[(ty*8+i)*129 + tx*8 + j] = acc[i][j];
        __syncthreads();
        if (tid < 128) {
            float* row = Ss + tid*129;
            float mold = mrow[tid];
            float mx = mold;
            for (int k=0;k<128;k++) mx = fmaxf(mx, row[k]);
            float corr = expf(mold - mx);
            float s = 0.f;
            for (int k=0;k<128;k++) { float e = expf(row[k]-mx); row[k]=e; s += e; }
            lrow[tid] = lrow[tid]*corr + s;
            mrow[tid] = mx;
            crow[tid] = corr;
        }
        __syncthreads();
        float corr = crow[orow];
        #pragma unroll
        for (int c=0;c<32;c++) o[c] *= corr;
        for (int k=0;k<128;k++) {
            float p = Ss[orow*129 + k];
            const float* vp = Vs + k*65 + cb;
            #pragma unroll
            for (int c=0;c<32;c++) o[c] += p*vp[c];
        }
    }
    __syncthreads();
    float inv = 1.0f / lrow[orow];
    float* outp = g_attnh + (size_t)(b*NQQ + qt*128 + orow)*512 + h*64 + cb;
    #pragma unroll
    for (int c=0;c<32;c++) outp[c] = o[c]*inv;
}

// ---------------- scatter-add heavy rows into output ----------------
__global__ void scatter_kernel(float* __restrict__ out)
{
    int rowi = blockIdx.x;               // 0..B*NQ-1
    int b = rowi >> 10;
    int dst = g_idxq[rowi];
    float4* o = (float4*)(out + ((size_t)b*NN + dst)*DD);
    const float4* s = (const float4*)(g_hrows + (size_t)rowi*DD);
    float4 a = o[threadIdx.x];
    float4 v = s[threadIdx.x];
    a.x += v.x; a.y += v.y; a.z += v.z; a.w += v.w;
    o[threadIdx.x] = a;
}

// ---------------- launch ----------------
extern "C" void kernel_launch(void* const* d_in, const int* in_sizes, int n_in,
                              void* d_out, int out_size)
{
    const float* x       = (const float*)d_in[0];
    const float* gamma_l = (const float*)d_in[1];
    const float* wq_l    = (const float*)d_in[2];
    const float* wkv_l   = (const float*)d_in[3];
    const float* wo_l    = (const float*)d_in[4];
    const float* qtok    = (const float*)d_in[5];
    const float* ktok    = (const float*)d_in[6];
    const float* gamma_h = (const float*)d_in[7];
    const float* wq_h    = (const float*)d_in[8];
    const float* wkv_h   = (const float*)d_in[9];
    const float* wo_h    = (const float*)d_in[10];
    float* out = (float*)d_out;

    float *p_rn, *p_qkv, *p_attnl, *p_rnq, *p_rnkv, *p_qh, *p_kvh, *p_attnh, *p_hrows;
    float *p_Wl, *p_Wqh, *p_Wkvh;
    cudaGetSymbolAddress((void**)&p_rn,    g_rn);
    cudaGetSymbolAddress((void**)&p_qkv,   g_qkv);
    cudaGetSymbolAddress((void**)&p_attnl, g_attnl);
    cudaGetSymbolAddress((void**)&p_rnq,   g_rnq);
    cudaGetSymbolAddress((void**)&p_rnkv,  g_rnkv);
    cudaGetSymbolAddress((void**)&p_qh,    g_qh);
    cudaGetSymbolAddress((void**)&p_kvh,   g_kvh);
    cudaGetSymbolAddress((void**)&p_attnh, g_attnh);
    cudaGetSymbolAddress((void**)&p_hrows, g_hrows);
    cudaGetSymbolAddress((void**)&p_Wl,    g_Wl);
    cudaGetSymbolAddress((void**)&p_Wqh,   g_Wqh);
    cudaGetSymbolAddress((void**)&p_Wkvh,  g_Wkvh);

    const int SMEM_SORT  = 8192 * 8;                              // 64 KB
    const int SMEM_WIN   = (3*128*65 + 128*129) * 4;              // 165888
    const int SMEM_HEAVY = (3*128*65 + 128*129 + 3*128) * 4;      // 167424
    cudaFuncSetAttribute(coor_topk_kernel, cudaFuncAttributeMaxDynamicSharedMemorySize, SMEM_SORT);
    cudaFuncSetAttribute(winattn_kernel,   cudaFuncAttributeMaxDynamicSharedMemorySize, SMEM_WIN);
    cudaFuncSetAttribute(heavyattn_kernel, cudaFuncAttributeMaxDynamicSharedMemorySize, SMEM_HEAVY);

    // 1) weight prep (fold gammas, transpose wkv_heavy)
    {
        int tot = DD*1536 + DD*HIDD + DD*1024;
        prep_weights_kernel<<<(tot+255)/256, 256>>>(gamma_l, wq_l, wkv_l, gamma_h, wq_h, wkv_h);
    }
    // 2) rmsnorm of all tokens
    rmsnorm_kernel<<<BB*NN, 256>>>(x);
    // 3) routing scores (raw x)
    routing_kernel<<<BB*NN/8, 256>>>(x, qtok, ktok);
    // 4) coor_descent + exact top-k selection
    coor_topk_kernel<<<dim3(2, BB), 1024, SMEM_SORT>>>();
    // 5) gather routed normalized rows
    gather_kernel<<<BB*NQQ,  256>>>(0);
    gather_kernel<<<BB*NKVV, 256>>>(1);
    // 6) light qkv projection (fused wq|wkv)
    sgemm_kernel<<<dim3(1536/128, (BB*NN)/128), 256>>>(p_rn, p_Wl, p_qkv, BB*NN, 1536, DD);
    // 7) light windowed attention
    winattn_kernel<<<BB*(NN/WINN)*NHEAD, 256, SMEM_WIN>>>();
    // 8) light output projection -> d_out (writes every element)
    sgemm_kernel<<<dim3(DD/128, (BB*NN)/128), 256>>>(p_attnl, wo_l, out, BB*NN, DD, HIDD);
    // 9) heavy projections
    sgemm_kernel<<<dim3(HIDD/128, (BB*NQQ)/128), 256>>>(p_rnq,  p_Wqh,  p_qh,  BB*NQQ,  HIDD, DD);
    sgemm_kernel<<<dim3(1024/128, (BB*NKVV)/128), 256>>>(p_rnkv, p_Wkvh, p_kvh, BB*NKVV, 1024, DD);
    // 10) heavy attention (flash over 2048 kv)
    heavyattn_kernel<<<BB*NHEAD*(NQQ/128), 256, SMEM_HEAVY>>>();
    // 11) heavy output projection
    sgemm_kernel<<<dim3(DD/128, (BB*NQQ)/128), 256>>>(p_attnh, wo_h, p_hrows, BB*NQQ, DD, HIDD);
    // 12) scatter-add into output
    scatter_kernel<<<BB*NQQ, 256>>>(out);
}